// round 12
// baseline (speedup 1.0000x reference)
#include <cuda_runtime.h>
#include <stdint.h>

// out[i] = in[i] + 0.1*sqrt(2)*erfinv(u(i)), matching
// jax.random.normal(jax.random.key(42), (64,3,512,512), f32),
// jax_threefry_partitionable=True:
//   (y0,y1) = threefry2x32((0,42),(0,i));  bits = y0 ^ y1
//   u = fma(float(bits), 2^-31, LO), LO=-0.99999994
//   noise = 0.1*sqrt(2)*erfinv(u)  [Giles; central poly deg 4, scale folded]
//
// alu pipe (SHF+LOP3) is the 84.7% binder; ~29 integer adds/elem are the only
// movable alu load. This round: FULL migration of every add to IMAD
// (FMAHeavy pipe) via inline-asm mad.lo.u32 with all-register operands and
// constants hoisted once per thread into a struct (the R4 recipe, which
// verifiably moved alu 86.9 -> 76.8; R8/R11 variants that mixed patterns or
// used C-level *one got strength-reduced back).

__device__ __forceinline__ uint32_t mad1(uint32_t a, uint32_t b, uint32_t c) {
    uint32_t d;
    asm("mad.lo.u32 %0, %1, %2, %3;" : "=r"(d) : "r"(a), "r"(b), "r"(c));
    return d;
}

struct TFC {
    uint32_t one;    // 1
    uint32_t k1;     // 42
    uint32_t k2;     // 0x1BD11BF0
    uint32_t k2p1;   // k2 + 1
    uint32_t c2;     // 2
    uint32_t c45;    // 45
    uint32_t k2p4;   // k2 + 4
    uint32_t c5;     // 5
};

// 20-round threefry2x32 on (0, ctr), v = ctr + 42 (key-injection 0 applied).
// Returns x0 ^ x1 after the final injection. All adds on the fmaheavy pipe.
__device__ __forceinline__ uint32_t tf_bits(uint32_t v, const TFC& K) {
#define TF_RND(r) { x0 = mad1(x1, K.one, x0); \
                    x1 = __funnelshift_l(x1, x1, (r)) ^ x0; }
    // round 1 (x0 starts at 0): x0 = v; x1 = rotl(v,13)^v
    uint32_t x0 = v;
    uint32_t x1 = __funnelshift_l(v, v, 13) ^ v;
    TF_RND(15) TF_RND(26) TF_RND(6)
    // inj1: x1 += k2+1; x0 = (x0 + 42) + x1
    x1 = mad1(K.one, K.k2p1, x1);
    x0 = mad1(K.one, K.k1, x0);  x0 = mad1(x1, K.one, x0);
    x1 = __funnelshift_l(x1, x1, 17) ^ x0;
    TF_RND(29) TF_RND(16) TF_RND(24)
    // inj2: x1 += 2; x0 = (x0 + k2) + x1
    x1 = mad1(K.one, K.c2, x1);
    x0 = mad1(K.one, K.k2, x0);  x0 = mad1(x1, K.one, x0);
    x1 = __funnelshift_l(x1, x1, 13) ^ x0;
    TF_RND(15) TF_RND(26) TF_RND(6)
    // inj3: x1 += 45; x0 += x1
    x1 = mad1(K.one, K.c45, x1);
    x0 = mad1(x1, K.one, x0);
    x1 = __funnelshift_l(x1, x1, 17) ^ x0;
    TF_RND(29) TF_RND(16) TF_RND(24)
    // inj4: x1 += k2+4; x0 = (x0 + 42) + x1
    x1 = mad1(K.one, K.k2p4, x1);
    x0 = mad1(K.one, K.k1, x0);  x0 = mad1(x1, K.one, x0);
    x1 = __funnelshift_l(x1, x1, 13) ^ x0;
    TF_RND(15) TF_RND(26) TF_RND(6)
    // final injection (x0+=k2, x1+=5), then lane XOR
    x0 = mad1(K.one, K.k2, x0);
    x1 = mad1(K.one, K.c5, x1);
#undef TF_RND
    return x0 ^ x1;
}

// bits -> u in [LO, 1): single I2F + FFMA. LO = nextafter(-1, 0).
__device__ __forceinline__ float bits_to_u(uint32_t y) {
    return fmaf((float)y, 4.656612873e-10f /* 2^-31 */, -0.99999994f);
}

// Rare tail (t = w-2.5 >= 2.5, i.e. |u| > 0.99663): full Giles tail poly,
// 0.1*sqrt(2) folded into coefficients.
__device__ __forceinline__ float noise_tail_f(float t, float u) {
    float s = sqrtf(t + 2.5f) - 3.0f;
    float p =       -2.83145467e-05f;
    p = fmaf(p, s,   1.42766481e-05f);
    p = fmaf(p, s,   1.90824894e-04f);
    p = fmaf(p, s,  -5.19499916e-04f);
    p = fmaf(p, s,   8.11690563e-04f);
    p = fmaf(p, s,  -1.07798485e-03f);
    p = fmaf(p, s,   1.33486521e-03f);
    p = fmaf(p, s,   1.41657794e-01f);
    p = fmaf(p, s,   4.00644237e-01f);
    return p * u;
}

// Shared per-thread body: 4 elements, one float4 in/out.
__device__ __forceinline__ float4 noise_body(float4 a, uint32_t c42,
                                             const TFC& K) {
    const float* av = &a.x;
    float u[4], t[4], o[4];
#pragma unroll
    for (int j = 0; j < 4; j++) {
        uint32_t y = tf_bits(c42 + (uint32_t)j, K);
        float uu = bits_to_u(y);
        float g = fmaf(-uu, uu, 1.0f);                // 1 - u^2, in (0, 1]
        float lg;
        asm("lg2.approx.f32 %0, %1;" : "=f"(lg) : "f"(g));
        float tt = fmaf(lg, -0.693147181f, -2.5f);    // w - 2.5
        // Central Giles poly deg 4, 0.1*sqrt(2) folded in.
        float p =        3.09122925e-05f;
        p = fmaf(p, tt, -1.77302644e-04f);
        p = fmaf(p, tt, -5.90813690e-04f);
        p = fmaf(p, tt,  3.48802861e-02f);
        p = fmaf(p, tt,  2.12331951e-01f);
        u[j] = uu; t[j] = tt;
        o[j] = fmaf(p, uu, av[j]);                    // out = a + p*u, fused
    }
    // One branch per thread for the rare tail (|u| > 0.99663).
    float mx = fmaxf(fmaxf(t[0], t[1]), fmaxf(t[2], t[3]));
    if (mx >= 2.5f) {
#pragma unroll
        for (int j = 0; j < 4; j++)
            if (t[j] >= 2.5f) o[j] = av[j] + noise_tail_f(t[j], u[j]);
    }
    float4 r;
    r.x = o[0]; r.y = o[1]; r.z = o[2]; r.w = o[3];
    return r;
}

// Guard-free kernel: grid*block == n4 exactly.
__global__ void __launch_bounds__(256)
noise_vec_exact(const float4* __restrict__ in, float4* __restrict__ out,
                uint32_t one) {
    int tid = blockIdx.x * blockDim.x + threadIdx.x;
    TFC K;
    K.one = one;
    K.k1   = 42u * one;
    K.k2   = 0x1BD11BF0u * one;
    K.k2p1 = K.k2 + 1u;
    K.c2   = 2u * one;
    K.c45  = 45u * one;
    K.k2p4 = K.k2 + 4u;
    K.c5   = 5u * one;
    out[tid] = noise_body(in[tid], 4u * (uint32_t)tid + 42u, K);
}

// Guarded variant (used only if n4 % 256 != 0).
__global__ void __launch_bounds__(256)
noise_vec_guard(const float4* __restrict__ in, float4* __restrict__ out,
                int n4, uint32_t one) {
    int tid = blockIdx.x * blockDim.x + threadIdx.x;
    if (tid >= n4) return;
    TFC K;
    K.one = one;
    K.k1   = 42u * one;
    K.k2   = 0x1BD11BF0u * one;
    K.k2p1 = K.k2 + 1u;
    K.c2   = 2u * one;
    K.c45  = 45u * one;
    K.k2p4 = K.k2 + 4u;
    K.c5   = 5u * one;
    out[tid] = noise_body(in[tid], 4u * (uint32_t)tid + 42u, K);
}

// Scalar fallback for n % 4 != 0 (not hit for this shape).
__global__ void noise_scalar_kernel(const float* __restrict__ in,
                                    float* __restrict__ out,
                                    unsigned int start, unsigned int n,
                                    uint32_t one) {
    unsigned int i = start + blockIdx.x * blockDim.x + threadIdx.x;
    if (i >= n) return;
    TFC K;
    K.one = one;
    K.k1   = 42u * one;
    K.k2   = 0x1BD11BF0u * one;
    K.k2p1 = K.k2 + 1u;
    K.c2   = 2u * one;
    K.c45  = 45u * one;
    K.k2p4 = K.k2 + 4u;
    K.c5   = 5u * one;
    uint32_t y = tf_bits(i + 42u, K);
    float u = bits_to_u(y);
    float g = fmaf(-u, u, 1.0f);
    float lg;
    asm("lg2.approx.f32 %0, %1;" : "=f"(lg) : "f"(g));
    float t = fmaf(lg, -0.693147181f, -2.5f);
    float p =        3.09122925e-05f;
    p = fmaf(p, t,  -1.77302644e-04f);
    p = fmaf(p, t,  -5.90813690e-04f);
    p = fmaf(p, t,   3.48802861e-02f);
    p = fmaf(p, t,   2.12331951e-01f);
    float nz = (t < 2.5f) ? p * u : noise_tail_f(t, u);
    out[i] = in[i] + nz;
}

extern "C" void kernel_launch(void* const* d_in, const int* in_sizes, int n_in,
                              void* d_out, int out_size) {
    const float* in = (const float*)d_in[0];
    float* out = (float*)d_out;

    unsigned int n = (unsigned int)in_sizes[0];  // 50331648
    int n4 = (int)(n / 4u);                      // 12582912 = 49152 * 256

    if (n4 > 0) {
        const int threads = 256;
        if (n4 % threads == 0) {
            noise_vec_exact<<<n4 / threads, threads>>>((const float4*)in,
                                                       (float4*)out, 1u);
        } else {
            int blocks = (n4 + threads - 1) / threads;
            noise_vec_guard<<<blocks, threads>>>((const float4*)in,
                                                 (float4*)out, n4, 1u);
        }
    }
    unsigned int done = (unsigned int)n4 * 4u;
    if (done < n) {
        unsigned int rem = n - done;
        noise_scalar_kernel<<<(rem + 255) / 256, 256>>>(in, out, done, n, 1u);
    }
}

// round 13
// speedup vs baseline: 1.0699x; 1.0699x over previous
#include <cuda_runtime.h>
#include <stdint.h>

// out[i] = in[i] + 0.1*sqrt(2)*erfinv(u(i)), matching
// jax.random.normal(jax.random.key(42), (64,3,512,512), f32),
// jax_threefry_partitionable=True:
//   (y0,y1) = threefry2x32((0,42),(0,i));  bits = y0 ^ y1
//   u = fma(float(bits), 2^-31, LO), LO=-0.99999994
//   noise = 0.1*sqrt(2)*erfinv(u)  [Giles; central poly deg 4, scale folded]
//
// Champion body (R10/R11, alu-pipe-bound at ~85%): plain adds (ptxas
// alternates IADD3/IMAD optimally -- forced-IMAD falsified 4x), 3-input
// IADD3 key injections, funnelshift rotates, I2F bits->u, fused out-add.
// This round: 8 elements/thread to amortize per-thread overhead (~1.3%)
// and feed the scheduler 8 independent hash chains.

// 20-round threefry2x32 on (0, ctr), v = ctr + 42 (key-injection 0 applied).
// Returns x0 ^ x1 after the final injection.
__device__ __forceinline__ uint32_t tf_bits(uint32_t v) {
#define TF_RND(r) { x0 += x1; x1 = __funnelshift_l(x1, x1, (r)) ^ x0; }
    // round 1 (x0 starts at 0): x0 = v; x1 = rotl(v,13)^v
    uint32_t x0 = v;
    uint32_t x1 = __funnelshift_l(v, v, 13) ^ v;
    TF_RND(15) TF_RND(26) TF_RND(6)
    // inj1 (x0+=42, x1+=k2+1) merged into round 5's x0-add (3-input IADD3)
    x1 += 0x1BD11BF1u;                      // k2 + 1
    x0 = x0 + 42u + x1;
    x1 = __funnelshift_l(x1, x1, 17) ^ x0;
    TF_RND(29) TF_RND(16) TF_RND(24)
    // inj2 (x0+=k2, x1+=2) merged into round 9's x0-add
    x1 += 2u;
    x0 = x0 + 0x1BD11BF0u + x1;
    x1 = __funnelshift_l(x1, x1, 13) ^ x0;
    TF_RND(15) TF_RND(26) TF_RND(6)
    // inj3 (x0+=0, x1+=45)
    x1 += 45u;
    x0 = x0 + x1;
    x1 = __funnelshift_l(x1, x1, 17) ^ x0;
    TF_RND(29) TF_RND(16) TF_RND(24)
    // inj4 (x0+=42, x1+=k2+4) merged into round 17's x0-add
    x1 += 0x1BD11BF4u;                      // k2 + 4
    x0 = x0 + 42u + x1;
    x1 = __funnelshift_l(x1, x1, 13) ^ x0;
    TF_RND(15) TF_RND(26) TF_RND(6)
    // final injection (x0+=k2, x1+=5), then lane XOR
    return (x0 + 0x1BD11BF0u) ^ (x1 + 5u);
#undef TF_RND
}

// bits -> u in [LO, 1): single I2F + FFMA. LO = nextafter(-1, 0).
__device__ __forceinline__ float bits_to_u(uint32_t y) {
    return fmaf((float)y, 4.656612873e-10f /* 2^-31 */, -0.99999994f);
}

// Rare tail (t = w-2.5 >= 2.5, i.e. |u| > 0.99663): full Giles tail poly,
// 0.1*sqrt(2) folded into coefficients.
__device__ __forceinline__ float noise_tail_f(float t, float u) {
    float s = sqrtf(t + 2.5f) - 3.0f;
    float p =       -2.83145467e-05f;
    p = fmaf(p, s,   1.42766481e-05f);
    p = fmaf(p, s,   1.90824894e-04f);
    p = fmaf(p, s,  -5.19499916e-04f);
    p = fmaf(p, s,   8.11690563e-04f);
    p = fmaf(p, s,  -1.07798485e-03f);
    p = fmaf(p, s,   1.33486521e-03f);
    p = fmaf(p, s,   1.41657794e-01f);
    p = fmaf(p, s,   4.00644237e-01f);
    return p * u;
}

// Guard-free kernel: 8 elements/thread, grid*block*8 == n exactly.
__global__ void __launch_bounds__(256)
noise_vec8_exact(const float4* __restrict__ in, float4* __restrict__ out) {
    int tid = blockIdx.x * blockDim.x + threadIdx.x;
    float4 a0 = in[2 * tid];
    float4 a1 = in[2 * tid + 1];
    const float av[8] = {a0.x, a0.y, a0.z, a0.w, a1.x, a1.y, a1.z, a1.w};
    uint32_t c42 = 8u * (uint32_t)tid + 42u;     // ctr + key-injection 0

    float u[8], t[8], o[8];
#pragma unroll
    for (int j = 0; j < 8; j++) {
        uint32_t y = tf_bits(c42 + (uint32_t)j);
        float uu = bits_to_u(y);
        float g = fmaf(-uu, uu, 1.0f);                // 1 - u^2, in (0, 1]
        float lg;
        asm("lg2.approx.f32 %0, %1;" : "=f"(lg) : "f"(g));
        float tt = fmaf(lg, -0.693147181f, -2.5f);    // w - 2.5
        // Central Giles poly deg 4, 0.1*sqrt(2) folded in.
        float p =        3.09122925e-05f;
        p = fmaf(p, tt, -1.77302644e-04f);
        p = fmaf(p, tt, -5.90813690e-04f);
        p = fmaf(p, tt,  3.48802861e-02f);
        p = fmaf(p, tt,  2.12331951e-01f);
        u[j] = uu; t[j] = tt;
        o[j] = fmaf(p, uu, av[j]);                    // out = a + p*u, fused
    }

    // One branch per thread for the rare tail (|u| > 0.99663; P~2.7%/thread).
    float m01 = fmaxf(t[0], t[1]), m23 = fmaxf(t[2], t[3]);
    float m45 = fmaxf(t[4], t[5]), m67 = fmaxf(t[6], t[7]);
    float mx = fmaxf(fmaxf(m01, m23), fmaxf(m45, m67));
    if (mx >= 2.5f) {
#pragma unroll
        for (int j = 0; j < 8; j++)
            if (t[j] >= 2.5f) o[j] = av[j] + noise_tail_f(t[j], u[j]);
    }

    float4 r0, r1;
    r0.x = o[0]; r0.y = o[1]; r0.z = o[2]; r0.w = o[3];
    r1.x = o[4]; r1.y = o[5]; r1.z = o[6]; r1.w = o[7];
    out[2 * tid]     = r0;
    out[2 * tid + 1] = r1;
}

// 4-elem guarded fallback (used only if n doesn't split into exact 8x grid).
__global__ void __launch_bounds__(256)
noise_vec4_guard(const float4* __restrict__ in, float4* __restrict__ out,
                 int start4, int n4) {
    int tid = start4 + blockIdx.x * blockDim.x + threadIdx.x;
    if (tid >= n4) return;
    float4 a = in[tid];
    const float av[4] = {a.x, a.y, a.z, a.w};
    uint32_t c42 = 4u * (uint32_t)tid + 42u;
    float u[4], t[4], o[4];
#pragma unroll
    for (int j = 0; j < 4; j++) {
        uint32_t y = tf_bits(c42 + (uint32_t)j);
        float uu = bits_to_u(y);
        float g = fmaf(-uu, uu, 1.0f);
        float lg;
        asm("lg2.approx.f32 %0, %1;" : "=f"(lg) : "f"(g));
        float tt = fmaf(lg, -0.693147181f, -2.5f);
        float p =        3.09122925e-05f;
        p = fmaf(p, tt, -1.77302644e-04f);
        p = fmaf(p, tt, -5.90813690e-04f);
        p = fmaf(p, tt,  3.48802861e-02f);
        p = fmaf(p, tt,  2.12331951e-01f);
        u[j] = uu; t[j] = tt;
        o[j] = fmaf(p, uu, av[j]);
    }
    float mx = fmaxf(fmaxf(t[0], t[1]), fmaxf(t[2], t[3]));
    if (mx >= 2.5f) {
#pragma unroll
        for (int j = 0; j < 4; j++)
            if (t[j] >= 2.5f) o[j] = av[j] + noise_tail_f(t[j], u[j]);
    }
    float4 r;
    r.x = o[0]; r.y = o[1]; r.z = o[2]; r.w = o[3];
    out[tid] = r;
}

// Scalar fallback for n % 4 != 0 (not hit for this shape).
__global__ void noise_scalar_kernel(const float* __restrict__ in,
                                    float* __restrict__ out,
                                    unsigned int start, unsigned int n) {
    unsigned int i = start + blockIdx.x * blockDim.x + threadIdx.x;
    if (i >= n) return;
    uint32_t y = tf_bits(i + 42u);
    float u = bits_to_u(y);
    float g = fmaf(-u, u, 1.0f);
    float lg;
    asm("lg2.approx.f32 %0, %1;" : "=f"(lg) : "f"(g));
    float t = fmaf(lg, -0.693147181f, -2.5f);
    float p =        3.09122925e-05f;
    p = fmaf(p, t,  -1.77302644e-04f);
    p = fmaf(p, t,  -5.90813690e-04f);
    p = fmaf(p, t,   3.48802861e-02f);
    p = fmaf(p, t,   2.12331951e-01f);
    float nz = (t < 2.5f) ? p * u : noise_tail_f(t, u);
    out[i] = in[i] + nz;
}

extern "C" void kernel_launch(void* const* d_in, const int* in_sizes, int n_in,
                              void* d_out, int out_size) {
    const float* in = (const float*)d_in[0];
    float* out = (float*)d_out;

    unsigned int n = (unsigned int)in_sizes[0];  // 50331648
    const int threads = 256;

    unsigned int n8 = n / 8u;                    // 6291456 = 24576 * 256
    unsigned int done = 0;
    if (n8 >= (unsigned int)threads && (n8 % threads) == 0) {
        noise_vec8_exact<<<n8 / threads, threads>>>((const float4*)in,
                                                    (float4*)out);
        done = n8 * 8u;
    }
    // Remaining full float4 groups via guarded 4-elem kernel.
    unsigned int n4 = n / 4u;
    unsigned int start4 = done / 4u;
    if (start4 < n4) {
        unsigned int rem4 = n4 - start4;
        noise_vec4_guard<<<(rem4 + threads - 1) / threads, threads>>>(
            (const float4*)in, (float4*)out, (int)start4, (int)n4);
        done = n4 * 4u;
    }
    if (done < n) {
        unsigned int rem = n - done;
        noise_scalar_kernel<<<(rem + 255) / 256, 256>>>(in, out, done, n);
    }
}

// round 14
// speedup vs baseline: 1.1029x; 1.0308x over previous
#include <cuda_runtime.h>
#include <stdint.h>

// out[i] = in[i] + 0.1*sqrt(2)*erfinv(u(i)), matching
// jax.random.normal(jax.random.key(42), (64,3,512,512), f32),
// jax_threefry_partitionable=True:
//   (y0,y1) = threefry2x32((0,42),(0,i));  bits = y0 ^ y1
//   u = fma(float_rd(bits), 2^-31, LO), LO=-0.99999994  (round-down I2F
//     guarantees u < 1 -> g = 1-u^2 > 0, no NaN from lg2)
//   noise = 0.1*sqrt(2)*erfinv(u), Giles poly evaluated directly in
//   L = lg2(1-u^2) (t = -ln2*L - 2.5 folded into coefficients), central
//   branch truncated to degree 3.
//
// Pipe model (validated R13): alu pipe carries exactly the irreducible
// 20 SHF + 20 LOP3 per element (ptxas auto-places all adds on IMAD);
// time tracks total issue slots at ~1.9us/slot. This round: -2 fp slots.

// 20-round threefry2x32 on (0, ctr), v = ctr + 42 (key-injection 0 applied).
// Returns x0 ^ x1 after the final injection.
__device__ __forceinline__ uint32_t tf_bits(uint32_t v) {
#define TF_RND(r) { x0 += x1; x1 = __funnelshift_l(x1, x1, (r)) ^ x0; }
    // round 1 (x0 starts at 0): x0 = v; x1 = rotl(v,13)^v
    uint32_t x0 = v;
    uint32_t x1 = __funnelshift_l(v, v, 13) ^ v;
    TF_RND(15) TF_RND(26) TF_RND(6)
    // inj1 (x0+=42, x1+=k2+1) merged into round 5's x0-add (3-input IADD3)
    x1 += 0x1BD11BF1u;                      // k2 + 1
    x0 = x0 + 42u + x1;
    x1 = __funnelshift_l(x1, x1, 17) ^ x0;
    TF_RND(29) TF_RND(16) TF_RND(24)
    // inj2 (x0+=k2, x1+=2) merged into round 9's x0-add
    x1 += 2u;
    x0 = x0 + 0x1BD11BF0u + x1;
    x1 = __funnelshift_l(x1, x1, 13) ^ x0;
    TF_RND(15) TF_RND(26) TF_RND(6)
    // inj3 (x0+=0, x1+=45)
    x1 += 45u;
    x0 = x0 + x1;
    x1 = __funnelshift_l(x1, x1, 17) ^ x0;
    TF_RND(29) TF_RND(16) TF_RND(24)
    // inj4 (x0+=42, x1+=k2+4) merged into round 17's x0-add
    x1 += 0x1BD11BF4u;                      // k2 + 4
    x0 = x0 + 42u + x1;
    x1 = __funnelshift_l(x1, x1, 13) ^ x0;
    TF_RND(15) TF_RND(26) TF_RND(6)
    // final injection (x0+=k2, x1+=5), then lane XOR
    return (x0 + 0x1BD11BF0u) ^ (x1 + 5u);
#undef TF_RND
}

// bits -> u in [LO, 1): round-DOWN I2F keeps u < 1 strictly (y>=2^32-128
// would otherwise round up to 2^32 and push u to 1.00000006 -> g<0 -> NaN).
__device__ __forceinline__ float bits_to_u(uint32_t y) {
    return fmaf(__uint2float_rd(y), 4.656612873e-10f /* 2^-31 */,
                -0.99999994f);
}

// Rare tail (L <= -7.2134752, i.e. w >= 5, |u| > 0.99663): full Giles tail
// poly, 0.1*sqrt(2) folded into coefficients. L = lg2(1-u^2).
__device__ __forceinline__ float noise_tail_L(float L, float u) {
    float w = -0.693147181f * L;
    float s = sqrtf(w) - 3.0f;
    float p =       -2.83145467e-05f;
    p = fmaf(p, s,   1.42766481e-05f);
    p = fmaf(p, s,   1.90824894e-04f);
    p = fmaf(p, s,  -5.19499916e-04f);
    p = fmaf(p, s,   8.11690563e-04f);
    p = fmaf(p, s,  -1.07798485e-03f);
    p = fmaf(p, s,   1.33486521e-03f);
    p = fmaf(p, s,   1.41657794e-01f);
    p = fmaf(p, s,   4.00644237e-01f);
    return p * u;
}

// Central branch: deg-3 poly in L (Giles central poly with t = -ln2*L - 2.5
// folded in, deg-4 term dropped; 0.1*sqrt(2) folded in). noise = q(L)*u.
#define Q3  5.9046144e-5f
#define Q2  3.5503370e-4f
#define Q1 -2.39205466e-2f
#define Q0  1.24209004e-1f
#define L_TAIL -7.2134752f

// Guard-free kernel: 8 elements/thread, grid*block*8 == n exactly.
__global__ void __launch_bounds__(256)
noise_vec8_exact(const float4* __restrict__ in, float4* __restrict__ out) {
    int tid = blockIdx.x * blockDim.x + threadIdx.x;
    float4 a0 = in[2 * tid];
    float4 a1 = in[2 * tid + 1];
    const float av[8] = {a0.x, a0.y, a0.z, a0.w, a1.x, a1.y, a1.z, a1.w};
    uint32_t c42 = 8u * (uint32_t)tid + 42u;     // ctr + key-injection 0

    float u[8], Ls[8], o[8];
#pragma unroll
    for (int j = 0; j < 8; j++) {
        uint32_t y = tf_bits(c42 + (uint32_t)j);
        float uu = bits_to_u(y);
        float g = fmaf(-uu, uu, 1.0f);                // 1 - u^2, > 0
        float L;
        asm("lg2.approx.f32 %0, %1;" : "=f"(L) : "f"(g));
        float q = fmaf(Q3, L, Q2);
        q = fmaf(q, L, Q1);
        q = fmaf(q, L, Q0);
        u[j] = uu; Ls[j] = L;
        o[j] = fmaf(q, uu, av[j]);                    // out = a + q*u, fused
    }

    // One branch per thread for the rare tail (P ~ 2.7%/thread).
    float m01 = fminf(Ls[0], Ls[1]), m23 = fminf(Ls[2], Ls[3]);
    float m45 = fminf(Ls[4], Ls[5]), m67 = fminf(Ls[6], Ls[7]);
    float mn = fminf(fminf(m01, m23), fminf(m45, m67));
    if (mn <= L_TAIL) {
#pragma unroll
        for (int j = 0; j < 8; j++)
            if (Ls[j] <= L_TAIL) o[j] = av[j] + noise_tail_L(Ls[j], u[j]);
    }

    float4 r0, r1;
    r0.x = o[0]; r0.y = o[1]; r0.z = o[2]; r0.w = o[3];
    r1.x = o[4]; r1.y = o[5]; r1.z = o[6]; r1.w = o[7];
    out[2 * tid]     = r0;
    out[2 * tid + 1] = r1;
}

// 4-elem guarded fallback (used only if n doesn't split into exact 8x grid).
__global__ void __launch_bounds__(256)
noise_vec4_guard(const float4* __restrict__ in, float4* __restrict__ out,
                 int start4, int n4) {
    int tid = start4 + blockIdx.x * blockDim.x + threadIdx.x;
    if (tid >= n4) return;
    float4 a = in[tid];
    const float av[4] = {a.x, a.y, a.z, a.w};
    uint32_t c42 = 4u * (uint32_t)tid + 42u;
    float u[4], Ls[4], o[4];
#pragma unroll
    for (int j = 0; j < 4; j++) {
        uint32_t y = tf_bits(c42 + (uint32_t)j);
        float uu = bits_to_u(y);
        float g = fmaf(-uu, uu, 1.0f);
        float L;
        asm("lg2.approx.f32 %0, %1;" : "=f"(L) : "f"(g));
        float q = fmaf(Q3, L, Q2);
        q = fmaf(q, L, Q1);
        q = fmaf(q, L, Q0);
        u[j] = uu; Ls[j] = L;
        o[j] = fmaf(q, uu, av[j]);
    }
    float mn = fminf(fminf(Ls[0], Ls[1]), fminf(Ls[2], Ls[3]));
    if (mn <= L_TAIL) {
#pragma unroll
        for (int j = 0; j < 4; j++)
            if (Ls[j] <= L_TAIL) o[j] = av[j] + noise_tail_L(Ls[j], u[j]);
    }
    float4 r;
    r.x = o[0]; r.y = o[1]; r.z = o[2]; r.w = o[3];
    out[tid] = r;
}

// Scalar fallback for n % 4 != 0 (not hit for this shape).
__global__ void noise_scalar_kernel(const float* __restrict__ in,
                                    float* __restrict__ out,
                                    unsigned int start, unsigned int n) {
    unsigned int i = start + blockIdx.x * blockDim.x + threadIdx.x;
    if (i >= n) return;
    uint32_t y = tf_bits(i + 42u);
    float u = bits_to_u(y);
    float g = fmaf(-u, u, 1.0f);
    float L;
    asm("lg2.approx.f32 %0, %1;" : "=f"(L) : "f"(g));
    float q = fmaf(Q3, L, Q2);
    q = fmaf(q, L, Q1);
    q = fmaf(q, L, Q0);
    float nz = (L > L_TAIL) ? q * u : noise_tail_L(L, u);
    out[i] = in[i] + nz;
}

extern "C" void kernel_launch(void* const* d_in, const int* in_sizes, int n_in,
                              void* d_out, int out_size) {
    const float* in = (const float*)d_in[0];
    float* out = (float*)d_out;

    unsigned int n = (unsigned int)in_sizes[0];  // 50331648
    const int threads = 256;

    unsigned int n8 = n / 8u;                    // 6291456 = 24576 * 256
    unsigned int done = 0;
    if (n8 >= (unsigned int)threads && (n8 % threads) == 0) {
        noise_vec8_exact<<<n8 / threads, threads>>>((const float4*)in,
                                                    (float4*)out);
        done = n8 * 8u;
    }
    unsigned int n4 = n / 4u;
    unsigned int start4 = done / 4u;
    if (start4 < n4) {
        unsigned int rem4 = n4 - start4;
        noise_vec4_guard<<<(rem4 + threads - 1) / threads, threads>>>(
            (const float4*)in, (float4*)out, (int)start4, (int)n4);
        done = n4 * 4u;
    }
    if (done < n) {
        unsigned int rem = n - done;
        noise_scalar_kernel<<<(rem + 255) / 256, 256>>>(in, out, done, n);
    }
}